// round 6
// baseline (speedup 1.0000x reference)
#include <cuda_runtime.h>
#include <cuda_bf16.h>
#include <math.h>

#define DIMN 3072
#define HEADS 24
#define HD 128
#define BATCH 2
#define S_IMG 1024
#define S_TXT 512
#define SEQ 1536
#define SCALE 0.08838834764831845f   // 1/sqrt(128)

// ---------------- scratch ----------------
__device__ float g_qbuf[(size_t)BATCH * SEQ * DIMN];
__device__ float g_kbuf[(size_t)BATCH * SEQ * DIMN];
__device__ float g_vbuf[(size_t)BATCH * SEQ * DIMN];
__device__ float g_obuf[(size_t)BATCH * SEQ * DIMN];

__device__ __forceinline__ unsigned f2tf(float f) {
    unsigned u;
    asm("cvt.rna.tf32.f32 %0, %1;" : "=r"(u) : "f"(f));
    return u;
}

__device__ __forceinline__ void mma_tf32(float& d0, float& d1, float& d2, float& d3,
                                         unsigned a0, unsigned a1, unsigned a2, unsigned a3,
                                         unsigned b0, unsigned b1)
{
    asm volatile("mma.sync.aligned.m16n8k8.row.col.f32.tf32.tf32.f32 "
                 "{%0,%1,%2,%3}, {%4,%5,%6,%7}, {%8,%9}, {%0,%1,%2,%3};\n"
                 : "+f"(d0), "+f"(d1), "+f"(d2), "+f"(d3)
                 : "r"(a0), "r"(a1), "r"(a2), "r"(a3), "r"(b0), "r"(b1));
}

__device__ __forceinline__ unsigned s2u(const void* p) {
    unsigned r;
    asm("{.reg .u64 t; cvta.to.shared.u64 t, %1; cvt.u32.u64 %0, t;}" : "=r"(r) : "l"(p));
    return r;
}
__device__ __forceinline__ void cpa16(unsigned dst, const void* src) {
    asm volatile("cp.async.cg.shared.global [%0], [%1], 16;" :: "r"(dst), "l"(src));
}
__device__ __forceinline__ void cp_commit() {
    asm volatile("cp.async.commit_group;");
}
template <int N> __device__ __forceinline__ void cp_wait() {
    asm volatile("cp.async.wait_group %0;" :: "n"(N));
}

// ---------------- tf32 tensor-core GEMM: C = A @ W + bias ----------------
// 512 threads, 16 warps (4x4), warp tile 32x32 -> 32 accumulators/thread.
#define GA_LD 36
#define GB_LD 136
#define NSTAGE 3
#define ASTAGE (128 * GA_LD)
#define BSTAGE (32 * GB_LD)

__global__ __launch_bounds__(512) void gemm_tf32(
    const float* __restrict__ A,
    const float* __restrict__ W0, const float* __restrict__ W1, const float* __restrict__ W2,
    const float* __restrict__ b0_, const float* __restrict__ b1_, const float* __restrict__ b2_,
    float* __restrict__ C0, float* __restrict__ C1, float* __restrict__ C2,
    int S_part, int in_sb, int in_off, int out_sb, int out_off, int cvt_mask)
{
    extern __shared__ float sm[];
    float* As = sm;
    float* Bs = sm + NSTAGE * ASTAGE;

    const int z = blockIdx.z;
    const float* W    = (z == 0) ? W0 : (z == 1) ? W1 : W2;
    const float* bias = (z == 0) ? b0_ : (z == 1) ? b1_ : b2_;
    float* C          = (z == 0) ? C0 : (z == 1) ? C1 : C2;
    const bool do_cvt = (cvt_mask >> z) & 1;

    const int t = threadIdx.x;
    const int lane = t & 31, w = t >> 5;
    const int g = lane >> 2, tig = lane & 3;
    const int wm = w >> 2, wn = w & 3;          // 4x4 warp grid
    const int bm = blockIdx.y * 128;
    const int bn = blockIdx.x * 128;

    // gmem sources: 2 float4 per thread per tile (A: 1024 float4, B: 1024 float4)
    const float* Aptr[2];
    #pragma unroll
    for (int j = 0; j < 2; j++) {
        int i = j * 512 + t;
        int r = i >> 3;                          // 0..127
        int gr = bm + r;
        int ab = gr / S_part, as_ = gr - ab * S_part;
        Aptr[j] = A + (size_t)(ab * in_sb + in_off + as_) * DIMN + ((i & 7) << 2);
    }
    const float* Bptr[2];
    #pragma unroll
    for (int j = 0; j < 2; j++) {
        int i = j * 512 + t;
        int r = i >> 5;                          // 0..31
        Bptr[j] = W + (size_t)r * DIMN + bn + ((i & 31) << 2);
    }

    const unsigned a_base = s2u(As);
    const unsigned b_base = s2u(Bs);
    unsigned a_off[2], b_off[2];
    #pragma unroll
    for (int j = 0; j < 2; j++) {
        int i = j * 512 + t;
        a_off[j] = a_base + (unsigned)((((i >> 3)) * GA_LD + ((i & 7) << 2)) * 4);
        b_off[j] = b_base + (unsigned)((((i >> 5)) * GB_LD + ((i & 31) << 2)) * 4);
    }

    const int NITER = DIMN / 32;                // 96

    #pragma unroll
    for (int s = 0; s < 2; s++) {
        int k0 = s * 32;
        #pragma unroll
        for (int j = 0; j < 2; j++) cpa16(a_off[j] + s * ASTAGE * 4, Aptr[j] + k0);
        #pragma unroll
        for (int j = 0; j < 2; j++) cpa16(b_off[j] + s * BSTAGE * 4, Bptr[j] + (size_t)k0 * DIMN);
        cp_commit();
    }

    float acc[2][4][4];
    #pragma unroll
    for (int mt = 0; mt < 2; mt++)
        #pragma unroll
        for (int nt = 0; nt < 4; nt++)
            #pragma unroll
            for (int i = 0; i < 4; i++) acc[mt][nt][i] = 0.f;

    int st = 0;
    for (int it = 0; it < NITER; it++) {
        // tail: no group committed after the final stage -> drain fully there
        if (it == NITER - 1) cp_wait<0>(); else cp_wait<1>();
        __syncthreads();

        const float* SA = As + st * ASTAGE + (wm * 32) * GA_LD;
        const float* SB = Bs + st * BSTAGE + wn * 32;
        #pragma unroll
        for (int ks = 0; ks < 4; ks++) {
            int kb = ks * 8;
            unsigned a[2][4];
            #pragma unroll
            for (int mt = 0; mt < 2; mt++) {
                const float* p = SA + (mt * 16 + g) * GA_LD + kb + tig;
                a[mt][0] = f2tf(p[0]);
                a[mt][1] = f2tf(p[8 * GA_LD]);
                a[mt][2] = f2tf(p[4]);
                a[mt][3] = f2tf(p[8 * GA_LD + 4]);
            }
            unsigned b[4][2];
            #pragma unroll
            for (int nt = 0; nt < 4; nt++) {
                const float* p = SB + (kb + tig) * GB_LD + nt * 8 + g;
                b[nt][0] = f2tf(p[0]);
                b[nt][1] = f2tf(p[4 * GB_LD]);
            }
            #pragma unroll
            for (int mt = 0; mt < 2; mt++)
                #pragma unroll
                for (int nt = 0; nt < 4; nt++)
                    mma_tf32(acc[mt][nt][0], acc[mt][nt][1], acc[mt][nt][2], acc[mt][nt][3],
                             a[mt][0], a[mt][1], a[mt][2], a[mt][3],
                             b[nt][0], b[nt][1]);
        }

        if (it + 2 < NITER) {
            int k0 = (it + 2) * 32;
            int ns = (st + 2) % NSTAGE;
            #pragma unroll
            for (int j = 0; j < 2; j++) cpa16(a_off[j] + ns * ASTAGE * 4, Aptr[j] + k0);
            #pragma unroll
            for (int j = 0; j < 2; j++) cpa16(b_off[j] + ns * BSTAGE * 4, Bptr[j] + (size_t)k0 * DIMN);
            cp_commit();
        }
        st = (st + 1) % NSTAGE;
    }

    #pragma unroll
    for (int mt = 0; mt < 2; mt++) {
        int r0 = bm + wm * 32 + mt * 16 + g;
        int r1 = r0 + 8;
        int cb0 = r0 / S_part, cs0 = r0 - cb0 * S_part;
        int cb1 = r1 / S_part, cs1 = r1 - cb1 * S_part;
        float* C0r = C + (size_t)(cb0 * out_sb + out_off + cs0) * DIMN;
        float* C1r = C + (size_t)(cb1 * out_sb + out_off + cs1) * DIMN;
        #pragma unroll
        for (int nt = 0; nt < 4; nt++) {
            int col = bn + wn * 32 + nt * 8 + 2 * tig;
            float bv0 = bias[col], bv1 = bias[col + 1];
            float v00 = acc[mt][nt][0] + bv0, v01 = acc[mt][nt][1] + bv1;
            float v10 = acc[mt][nt][2] + bv0, v11 = acc[mt][nt][3] + bv1;
            if (do_cvt) {
                v00 = __uint_as_float(f2tf(v00)); v01 = __uint_as_float(f2tf(v01));
                v10 = __uint_as_float(f2tf(v10)); v11 = __uint_as_float(f2tf(v11));
            }
            *(float2*)(C0r + col) = make_float2(v00, v01);
            *(float2*)(C1r + col) = make_float2(v10, v11);
        }
    }
}

// ---------------- per-head RMSNorm + RoPE (writes tf32; Q pre-scaled) ----------------
__global__ __launch_bounds__(128) void rmsrope_kernel(
    float* __restrict__ q, float* __restrict__ k,
    const float* __restrict__ cosb, const float* __restrict__ sinb,
    const float* __restrict__ gq, const float* __restrict__ gqc,
    const float* __restrict__ gk, const float* __restrict__ gkc)
{
    const int s = blockIdx.x;
    const int b = blockIdx.y;
    const int h = blockIdx.z % HEADS;
    const int which = blockIdx.z / HEADS;
    float* buf = which ? k : q;
    const float* g = which ? (s < S_TXT ? gkc : gk) : (s < S_TXT ? gqc : gq);
    const float post = which ? 1.0f : SCALE;
    const int d = threadIdx.x;

    const size_t base = ((size_t)(b * SEQ + s)) * DIMN + h * HD;
    float v = buf[base + d];
    float ss = v * v;
    #pragma unroll
    for (int o = 16; o; o >>= 1) ss += __shfl_xor_sync(0xffffffffu, ss, o);
    __shared__ float wsum[4];
    __shared__ float nbuf[HD];
    if ((d & 31) == 0) wsum[d >> 5] = ss;
    __syncthreads();
    float tot = wsum[0] + wsum[1] + wsum[2] + wsum[3];
    float r = rsqrtf(tot * (1.0f / HD) + 1e-6f);
    nbuf[d] = v * r * g[d];
    __syncthreads();
    if (d < 64) {
        float x1 = nbuf[2 * d], x2 = nbuf[2 * d + 1];
        float c = cosb[s * 64 + d], sn = sinb[s * 64 + d];
        buf[base + 2 * d]     = __uint_as_float(f2tf((x1 * c - x2 * sn) * post));
        buf[base + 2 * d + 1] = __uint_as_float(f2tf((x1 * sn + x2 * c) * post));
    }
}

// ---------------- flash attention (tf32 mma; inputs pre-converted) ----------------
#define QLD 132
#define KLD 132
#define VLD 136
#define PLD 68

__global__ __launch_bounds__(256) void attn_mma(
    const float* __restrict__ Q, const float* __restrict__ K,
    const float* __restrict__ V, float* __restrict__ O)
{
    extern __shared__ float sm[];
    float* Qs = sm;                       // 128 x 132 (tf32, pre-scaled by producer)
    float* Ks = Qs + 128 * QLD;           // 64 x 132 (tf32)
    float* Vs = Ks + 64 * KLD;            // 64 x 136 (tf32)
    float* Ps = Vs + 64 * VLD;            // 128 x 68

    const int t = threadIdx.x;
    const int lane = t & 31, w = t >> 5;
    const int g = lane >> 2, tig = lane & 3;
    const int mb = w * 16;
    const int m0 = blockIdx.x * 128;
    const int h = blockIdx.y;
    const int b = blockIdx.z;
    const size_t seqbase = (size_t)b * SEQ;

    const unsigned k_base = s2u(Ks);
    const unsigned v_base = s2u(Vs);

    const float* Qg = Q + (seqbase + m0) * DIMN + h * HD;
    for (int i = t; i < 128 * 32; i += 256) {
        int r = i >> 5, c4 = (i & 31) << 2;
        *(float4*)(Qs + r * QLD + c4) = *(const float4*)(Qg + (size_t)r * DIMN + c4);
    }

    {
        const float* Kg = K + seqbase * DIMN + h * HD;
        const float* Vg = V + seqbase * DIMN + h * HD;
        #pragma unroll
        for (int j = 0; j < 8; j++) {
            int idx = j * 256 + t;
            int r = idx >> 5, c = (idx & 31) << 2;
            cpa16(k_base + (unsigned)((r * KLD + c) * 4), Kg + (size_t)r * DIMN + c);
        }
        cp_commit();
        #pragma unroll
        for (int j = 0; j < 8; j++) {
            int idx = j * 256 + t;
            int r = idx >> 5, c = (idx & 31) << 2;
            cpa16(v_base + (unsigned)((r * VLD + c) * 4), Vg + (size_t)r * DIMN + c);
        }
        cp_commit();
    }

    float m0r = -1e30f, m1r = -1e30f, l0 = 0.f, l1 = 0.f;
    float o[16][4];
    #pragma unroll
    for (int nt = 0; nt < 16; nt++)
        #pragma unroll
        for (int i = 0; i < 4; i++) o[nt][i] = 0.f;

    for (int n0 = 0; n0 < SEQ; n0 += 64) {
        const bool has_next = (n0 + 64 < SEQ);
        cp_wait<1>();
        __syncthreads();

        // S = Q K^T (warp: 16x64)
        float s[8][4];
        #pragma unroll
        for (int nt = 0; nt < 8; nt++)
            #pragma unroll
            for (int i = 0; i < 4; i++) s[nt][i] = 0.f;
        #pragma unroll
        for (int kk = 0; kk < 16; kk++) {
            int kb = kk * 8;
            const float* pa = Qs + (mb + g) * QLD + kb + tig;
            unsigned a0 = __float_as_uint(pa[0]);
            unsigned a1 = __float_as_uint(pa[8 * QLD]);
            unsigned a2 = __float_as_uint(pa[4]);
            unsigned a3 = __float_as_uint(pa[8 * QLD + 4]);
            #pragma unroll
            for (int nt = 0; nt < 8; nt++) {
                const float* pb = Ks + (nt * 8 + g) * KLD + kb + tig;
                unsigned b0 = __float_as_uint(pb[0]);
                unsigned b1 = __float_as_uint(pb[4]);
                mma_tf32(s[nt][0], s[nt][1], s[nt][2], s[nt][3], a0, a1, a2, a3, b0, b1);
            }
        }
        __syncthreads();

        if (has_next) {
            const float* Kg = K + (seqbase + n0 + 64) * DIMN + h * HD;
            #pragma unroll
            for (int j = 0; j < 8; j++) {
                int idx = j * 256 + t;
                int r = idx >> 5, c = (idx & 31) << 2;
                cpa16(k_base + (unsigned)((r * KLD + c) * 4), Kg + (size_t)r * DIMN + c);
            }
            cp_commit();
        }

        // online softmax (registers)
        float mx0 = -1e30f, mx1 = -1e30f;
        #pragma unroll
        for (int nt = 0; nt < 8; nt++) {
            mx0 = fmaxf(mx0, fmaxf(s[nt][0], s[nt][1]));
            mx1 = fmaxf(mx1, fmaxf(s[nt][2], s[nt][3]));
        }
        mx0 = fmaxf(mx0, __shfl_xor_sync(0xffffffffu, mx0, 1));
        mx0 = fmaxf(mx0, __shfl_xor_sync(0xffffffffu, mx0, 2));
        mx1 = fmaxf(mx1, __shfl_xor_sync(0xffffffffu, mx1, 1));
        mx1 = fmaxf(mx1, __shfl_xor_sync(0xffffffffu, mx1, 2));
        float mn0 = fmaxf(m0r, mx0), mn1 = fmaxf(m1r, mx1);
        float sc0 = __expf(m0r - mn0), sc1 = __expf(m1r - mn1);
        m0r = mn0; m1r = mn1;
        float sum0 = 0.f, sum1 = 0.f;
        #pragma unroll
        for (int nt = 0; nt < 8; nt++) {
            s[nt][0] = __expf(s[nt][0] - mn0); sum0 += s[nt][0];
            s[nt][1] = __expf(s[nt][1] - mn0); sum0 += s[nt][1];
            s[nt][2] = __expf(s[nt][2] - mn1); sum1 += s[nt][2];
            s[nt][3] = __expf(s[nt][3] - mn1); sum1 += s[nt][3];
        }
        sum0 += __shfl_xor_sync(0xffffffffu, sum0, 1);
        sum0 += __shfl_xor_sync(0xffffffffu, sum0, 2);
        sum1 += __shfl_xor_sync(0xffffffffu, sum1, 1);
        sum1 += __shfl_xor_sync(0xffffffffu, sum1, 2);
        l0 = l0 * sc0 + sum0;
        l1 = l1 * sc1 + sum1;

        #pragma unroll
        for (int nt = 0; nt < 8; nt++) {
            *(float2*)(Ps + (mb + g) * PLD + nt * 8 + 2 * tig) =
                make_float2(__uint_as_float(f2tf(s[nt][0])), __uint_as_float(f2tf(s[nt][1])));
            *(float2*)(Ps + (mb + g + 8) * PLD + nt * 8 + 2 * tig) =
                make_float2(__uint_as_float(f2tf(s[nt][2])), __uint_as_float(f2tf(s[nt][3])));
        }
        #pragma unroll
        for (int nt = 0; nt < 16; nt++) {
            o[nt][0] *= sc0; o[nt][1] *= sc0;
            o[nt][2] *= sc1; o[nt][3] *= sc1;
        }

        if (has_next) cp_wait<1>(); else cp_wait<0>();
        __syncthreads();

        // O += P @ V (warp: 16x128)
        #pragma unroll
        for (int kk = 0; kk < 8; kk++) {
            int kb = kk * 8;
            const float* pa = Ps + (mb + g) * PLD + kb + tig;
            unsigned a0 = __float_as_uint(pa[0]);
            unsigned a1 = __float_as_uint(pa[8 * PLD]);
            unsigned a2 = __float_as_uint(pa[4]);
            unsigned a3 = __float_as_uint(pa[8 * PLD + 4]);
            #pragma unroll
            for (int nt = 0; nt < 16; nt++) {
                const float* pb = Vs + (kb + tig) * VLD + nt * 8 + g;
                unsigned b0 = __float_as_uint(pb[0]);
                unsigned b1 = __float_as_uint(pb[4 * VLD]);
                mma_tf32(o[nt][0], o[nt][1], o[nt][2], o[nt][3], a0, a1, a2, a3, b0, b1);
            }
        }
        __syncthreads();

        if (has_next) {
            const float* Vg = V + (seqbase + n0 + 64) * DIMN + h * HD;
            #pragma unroll
            for (int j = 0; j < 8; j++) {
                int idx = j * 256 + t;
                int r = idx >> 5, c = (idx & 31) << 2;
                cpa16(v_base + (unsigned)((r * VLD + c) * 4), Vg + (size_t)r * DIMN + c);
            }
            cp_commit();
        }
    }

    float inv0 = 1.f / l0, inv1 = 1.f / l1;
    float* Og = O + (seqbase + m0 + mb) * DIMN + h * HD;
    #pragma unroll
    for (int nt = 0; nt < 16; nt++) {
        int col = nt * 8 + 2 * tig;
        *(float2*)(Og + (size_t)g * DIMN + col) =
            make_float2(o[nt][0] * inv0, o[nt][1] * inv0);
        *(float2*)(Og + (size_t)(g + 8) * DIMN + col) =
            make_float2(o[nt][2] * inv1, o[nt][3] * inv1);
    }
}

// ---------------- launch ----------------
extern "C" void kernel_launch(void* const* d_in, const int* in_sizes, int n_in,
                              void* d_out, int out_size)
{
    const float* x        = (const float*)d_in[0];
    const float* ctx      = (const float*)d_in[1];
    const float* rope_cos = (const float*)d_in[2];
    const float* rope_sin = (const float*)d_in[3];
    const float* wq   = (const float*)d_in[4];
    const float* bq   = (const float*)d_in[5];
    const float* wk   = (const float*)d_in[6];
    const float* bk   = (const float*)d_in[7];
    const float* wv   = (const float*)d_in[8];
    const float* bv   = (const float*)d_in[9];
    const float* wqc  = (const float*)d_in[10];
    const float* bqc  = (const float*)d_in[11];
    const float* wkc  = (const float*)d_in[12];
    const float* bkc  = (const float*)d_in[13];
    const float* wvc  = (const float*)d_in[14];
    const float* bvc  = (const float*)d_in[15];
    const float* w_out     = (const float*)d_in[16];
    const float* b_out     = (const float*)d_in[17];
    const float* w_add_out = (const float*)d_in[18];
    const float* b_add_out = (const float*)d_in[19];
    const float* g_q  = (const float*)d_in[20];
    const float* g_k  = (const float*)d_in[21];
    const float* g_qc = (const float*)d_in[22];
    const float* g_kc = (const float*)d_in[23];
    float* out = (float*)d_out;

    float *qb, *kb, *vb, *ob;
    cudaGetSymbolAddress((void**)&qb, g_qbuf);
    cudaGetSymbolAddress((void**)&kb, g_kbuf);
    cudaGetSymbolAddress((void**)&vb, g_vbuf);
    cudaGetSymbolAddress((void**)&ob, g_obuf);

    const int smem_gemm = (NSTAGE * ASTAGE + NSTAGE * BSTAGE) * 4;
    const int smem_attn = (128 * QLD + 64 * KLD + 64 * VLD + 128 * PLD) * 4;
    cudaFuncSetAttribute(gemm_tf32, cudaFuncAttributeMaxDynamicSharedMemorySize, smem_gemm);
    cudaFuncSetAttribute(attn_mma, cudaFuncAttributeMaxDynamicSharedMemorySize, smem_attn);

    dim3 blk_g(512);
    dim3 blk_a(256);
    // fused QKV projections; V (z=2) epilogue rounds to tf32 for attention
    dim3 grid_ctx3(DIMN / 128, (BATCH * S_TXT) / 128, 3);
    dim3 grid_img3(DIMN / 128, (BATCH * S_IMG) / 128, 3);
    gemm_tf32<<<grid_ctx3, blk_g, smem_gemm>>>(ctx, wqc, wkc, wvc, bqc, bkc, bvc,
                                               qb, kb, vb, S_TXT, S_TXT, 0, SEQ, 0, 4);
    gemm_tf32<<<grid_img3, blk_g, smem_gemm>>>(x, wq, wk, wv, bq, bk, bv,
                                               qb, kb, vb, S_IMG, S_IMG, 0, SEQ, S_TXT, 4);

    dim3 grid_rr(SEQ, BATCH, 2 * HEADS);
    rmsrope_kernel<<<grid_rr, 128>>>(qb, kb, rope_cos, rope_sin, g_q, g_qc, g_k, g_kc);

    dim3 grid_at(SEQ / 128, HEADS, BATCH);
    attn_mma<<<grid_at, blk_a, smem_attn>>>(qb, kb, vb, ob);

    dim3 grid_txt(DIMN / 128, (BATCH * S_TXT) / 128, 1);
    dim3 grid_img(DIMN / 128, (BATCH * S_IMG) / 128, 1);
    gemm_tf32<<<grid_txt, blk_g, smem_gemm>>>(ob, w_add_out, w_add_out, w_add_out,
                                              b_add_out, b_add_out, b_add_out,
                                              out, out, out, S_TXT, SEQ, 0, S_TXT, 0, 0);
    gemm_tf32<<<grid_img, blk_g, smem_gemm>>>(ob, w_out, w_out, w_out,
                                              b_out, b_out, b_out,
                                              out + (size_t)BATCH * S_TXT * DIMN,
                                              out + (size_t)BATCH * S_TXT * DIMN,
                                              out + (size_t)BATCH * S_TXT * DIMN,
                                              S_IMG, SEQ, S_TXT, S_IMG, 0, 0);
}

// round 7
// speedup vs baseline: 1.1664x; 1.1664x over previous
#include <cuda_runtime.h>
#include <cuda_bf16.h>
#include <math.h>

#define DIMN 3072
#define HEADS 24
#define HD 128
#define BATCH 2
#define S_IMG 1024
#define S_TXT 512
#define SEQ 1536
#define SCALE 0.08838834764831845f   // 1/sqrt(128)
#define M2 (DIMN * DIMN)

// ---------------- scratch ----------------
__device__ float g_qbuf[(size_t)BATCH * SEQ * DIMN];
__device__ float g_kbuf[(size_t)BATCH * SEQ * DIMN];
__device__ float g_vtbuf[(size_t)BATCH * SEQ * DIMN];   // V transposed: [b][h][d][seq]
__device__ float g_obuf[(size_t)BATCH * SEQ * DIMN];
__device__ float g_wtf[(size_t)8 * M2];                 // tf32 weights
__device__ float g_xtf[(size_t)BATCH * S_IMG * DIMN];
__device__ float g_ctxtf[(size_t)BATCH * S_TXT * DIMN];

__device__ __forceinline__ unsigned f2tf(float f) {
    unsigned u;
    asm("cvt.rna.tf32.f32 %0, %1;" : "=r"(u) : "f"(f));
    return u;
}

__device__ __forceinline__ void mma_tf32(float& d0, float& d1, float& d2, float& d3,
                                         unsigned a0, unsigned a1, unsigned a2, unsigned a3,
                                         unsigned b0, unsigned b1)
{
    asm volatile("mma.sync.aligned.m16n8k8.row.col.f32.tf32.tf32.f32 "
                 "{%0,%1,%2,%3}, {%4,%5,%6,%7}, {%8,%9}, {%0,%1,%2,%3};\n"
                 : "+f"(d0), "+f"(d1), "+f"(d2), "+f"(d3)
                 : "r"(a0), "r"(a1), "r"(a2), "r"(a3), "r"(b0), "r"(b1));
}

__device__ __forceinline__ unsigned s2u(const void* p) {
    unsigned r;
    asm("{.reg .u64 t; cvta.to.shared.u64 t, %1; cvt.u32.u64 %0, t;}" : "=r"(r) : "l"(p));
    return r;
}
__device__ __forceinline__ void cpa16(unsigned dst, const void* src) {
    asm volatile("cp.async.cg.shared.global [%0], [%1], 16;" :: "r"(dst), "l"(src));
}
__device__ __forceinline__ void cp_commit() {
    asm volatile("cp.async.commit_group;");
}
template <int N> __device__ __forceinline__ void cp_wait() {
    asm volatile("cp.async.wait_group %0;" :: "n"(N));
}
__device__ __forceinline__ void ldm_x4(unsigned& r0, unsigned& r1, unsigned& r2, unsigned& r3,
                                       unsigned addr)
{
    asm volatile("ldmatrix.sync.aligned.m8n8.x4.shared.b16 {%0,%1,%2,%3}, [%4];"
                 : "=r"(r0), "=r"(r1), "=r"(r2), "=r"(r3) : "r"(addr));
}

// ---------------- tf32 pre-conversion ----------------
__global__ __launch_bounds__(256) void cvt_tf32(const float* __restrict__ in,
                                                float* __restrict__ out, int n4)
{
    int i = blockIdx.x * blockDim.x + threadIdx.x;
    int stride = gridDim.x * blockDim.x;
    for (; i < n4; i += stride) {
        float4 v = ((const float4*)in)[i];
        float4 o;
        o.x = __uint_as_float(f2tf(v.x));
        o.y = __uint_as_float(f2tf(v.y));
        o.z = __uint_as_float(f2tf(v.z));
        o.w = __uint_as_float(f2tf(v.w));
        ((float4*)out)[i] = o;
    }
}

// ---------------- tf32 tensor-core GEMM: C = A @ W + bias ----------------
// All A/W inputs pre-converted to tf32. Row maps per round 4.
#define GA_LD 36
#define GB_LD 136
#define NSTAGE 3
#define ASTAGE (128 * GA_LD)
#define BSTAGE (32 * GB_LD)

__global__ __launch_bounds__(256) void gemm_tf32(
    const float* __restrict__ A,
    const float* __restrict__ W0, const float* __restrict__ W1, const float* __restrict__ W2,
    const float* __restrict__ b0_, const float* __restrict__ b1_, const float* __restrict__ b2_,
    float* __restrict__ C0, float* __restrict__ C1, float* __restrict__ C2,
    int S_part, int in_sb, int in_off, int out_sb, int out_off, int cvt_mask, int vt_mask)
{
    extern __shared__ float sm[];
    float* As = sm;
    float* Bs = sm + NSTAGE * ASTAGE;

    const int z = blockIdx.z;
    const float* W    = (z == 0) ? W0 : (z == 1) ? W1 : W2;
    const float* bias = (z == 0) ? b0_ : (z == 1) ? b1_ : b2_;
    float* C          = (z == 0) ? C0 : (z == 1) ? C1 : C2;
    const bool do_cvt = (cvt_mask >> z) & 1;
    const bool do_vt  = (vt_mask >> z) & 1;

    const int t = threadIdx.x;
    const int lane = t & 31, w = t >> 5;
    const int g = lane >> 2, tig = lane & 3;
    const int wm = w >> 2, wn = w & 3;          // 2x4 warp grid, warp tile 64x32
    const int bm = blockIdx.y * 128;
    const int bn = blockIdx.x * 128;

    const float* Aptr[4];
    #pragma unroll
    for (int j = 0; j < 4; j++) {
        int r = 32 * j + (t >> 3);
        int gr = bm + r;
        int ab = gr / S_part, as_ = gr - ab * S_part;
        Aptr[j] = A + (size_t)(ab * in_sb + in_off + as_) * DIMN + ((t & 7) << 2);
    }
    const float* Bptr[4];
    #pragma unroll
    for (int j = 0; j < 4; j++) {
        int r = 8 * j + (t >> 5);
        Bptr[j] = W + (size_t)r * DIMN + bn + ((t & 31) << 2);
    }

    const unsigned a_base = s2u(As);
    const unsigned b_base = s2u(Bs);
    unsigned a_off[4], b_off[4];
    #pragma unroll
    for (int j = 0; j < 4; j++) {
        a_off[j] = a_base + (unsigned)(((32 * j + (t >> 3)) * GA_LD + ((t & 7) << 2)) * 4);
        b_off[j] = b_base + (unsigned)(((8 * j + (t >> 5)) * GB_LD + ((t & 31) << 2)) * 4);
    }
    // ldmatrix per-lane A address base: row = wm*64 + (lane&15), col-chunk = (lane>>4)*4
    const unsigned a_lm = a_base +
        (unsigned)((((wm * 64 + (lane & 15)) * GA_LD + ((lane >> 4) << 2))) * 4);

    const int NITER = DIMN / 32;                // 96

    #pragma unroll
    for (int s = 0; s < 2; s++) {
        int k0 = s * 32;
        #pragma unroll
        for (int j = 0; j < 4; j++) cpa16(a_off[j] + s * ASTAGE * 4, Aptr[j] + k0);
        #pragma unroll
        for (int j = 0; j < 4; j++) cpa16(b_off[j] + s * BSTAGE * 4, Bptr[j] + (size_t)k0 * DIMN);
        cp_commit();
    }

    float acc[4][4][4];
    #pragma unroll
    for (int mt = 0; mt < 4; mt++)
        #pragma unroll
        for (int nt = 0; nt < 4; nt++)
            #pragma unroll
            for (int i = 0; i < 4; i++) acc[mt][nt][i] = 0.f;

    int st = 0;
    for (int it = 0; it < NITER; it++) {
        // tail: drain fully on last iteration (no group committed after it)
        if (it == NITER - 1) cp_wait<0>(); else cp_wait<1>();
        __syncthreads();

        const unsigned a_st = a_lm + (unsigned)(st * ASTAGE * 4);
        const float* SB = Bs + st * BSTAGE + wn * 32;
        #pragma unroll
        for (int ks = 0; ks < 4; ks++) {
            int kb = ks * 8;
            unsigned a[4][4];
            #pragma unroll
            for (int mt = 0; mt < 4; mt++)
                ldm_x4(a[mt][0], a[mt][1], a[mt][2], a[mt][3],
                       a_st + (unsigned)((mt * 16 * GA_LD + kb) * 4));
            unsigned b[4][2];
            #pragma unroll
            for (int nt = 0; nt < 4; nt++) {
                const float* p = SB + (kb + tig) * GB_LD + nt * 8 + g;
                b[nt][0] = __float_as_uint(p[0]);
                b[nt][1] = __float_as_uint(p[4 * GB_LD]);
            }
            #pragma unroll
            for (int mt = 0; mt < 4; mt++)
                #pragma unroll
                for (int nt = 0; nt < 4; nt++)
                    mma_tf32(acc[mt][nt][0], acc[mt][nt][1], acc[mt][nt][2], acc[mt][nt][3],
                             a[mt][0], a[mt][1], a[mt][2], a[mt][3],
                             b[nt][0], b[nt][1]);
        }

        if (it + 2 < NITER) {
            int k0 = (it + 2) * 32;
            int ns = (st + 2) % NSTAGE;
            #pragma unroll
            for (int j = 0; j < 4; j++) cpa16(a_off[j] + ns * ASTAGE * 4, Aptr[j] + k0);
            #pragma unroll
            for (int j = 0; j < 4; j++) cpa16(b_off[j] + ns * BSTAGE * 4, Bptr[j] + (size_t)k0 * DIMN);
            cp_commit();
        }
        st = (st + 1) % NSTAGE;
    }

    #pragma unroll
    for (int mt = 0; mt < 4; mt++) {
        int r0 = bm + wm * 64 + mt * 16 + g;
        int r1 = r0 + 8;
        int cb0 = r0 / S_part, cs0 = r0 - cb0 * S_part;
        int cb1 = r1 / S_part, cs1 = r1 - cb1 * S_part;
        if (do_vt) {
            // transposed write: C[b][h][d][seq] (tf32 values)
            int s0 = out_off + cs0, s1 = out_off + cs1;
            #pragma unroll
            for (int nt = 0; nt < 4; nt++) {
                int col = bn + wn * 32 + nt * 8 + 2 * tig;
                int hh = col >> 7, d = col & 127;
                float bv0 = bias[col], bv1 = bias[col + 1];
                float* p0 = C + (((size_t)cb0 * HEADS + hh) * HD + d) * SEQ;
                float* p1 = C + (((size_t)cb1 * HEADS + hh) * HD + d) * SEQ;
                p0[s0]       = __uint_as_float(f2tf(acc[mt][nt][0] + bv0));
                p0[SEQ + s0] = __uint_as_float(f2tf(acc[mt][nt][1] + bv1));
                p1[s1]       = __uint_as_float(f2tf(acc[mt][nt][2] + bv0));
                p1[SEQ + s1] = __uint_as_float(f2tf(acc[mt][nt][3] + bv1));
            }
        } else {
            float* C0r = C + (size_t)(cb0 * out_sb + out_off + cs0) * DIMN;
            float* C1r = C + (size_t)(cb1 * out_sb + out_off + cs1) * DIMN;
            #pragma unroll
            for (int nt = 0; nt < 4; nt++) {
                int col = bn + wn * 32 + nt * 8 + 2 * tig;
                float bv0 = bias[col], bv1 = bias[col + 1];
                float v00 = acc[mt][nt][0] + bv0, v01 = acc[mt][nt][1] + bv1;
                float v10 = acc[mt][nt][2] + bv0, v11 = acc[mt][nt][3] + bv1;
                if (do_cvt) {
                    v00 = __uint_as_float(f2tf(v00)); v01 = __uint_as_float(f2tf(v01));
                    v10 = __uint_as_float(f2tf(v10)); v11 = __uint_as_float(f2tf(v11));
                }
                *(float2*)(C0r + col) = make_float2(v00, v01);
                *(float2*)(C1r + col) = make_float2(v10, v11);
            }
        }
    }
}

// ---------------- per-head RMSNorm + RoPE (writes tf32; Q pre-scaled) ----------------
__global__ __launch_bounds__(128) void rmsrope_kernel(
    float* __restrict__ q, float* __restrict__ k,
    const float* __restrict__ cosb, const float* __restrict__ sinb,
    const float* __restrict__ gq, const float* __restrict__ gqc,
    const float* __restrict__ gk, const float* __restrict__ gkc)
{
    const int s = blockIdx.x;
    const int b = blockIdx.y;
    const int h = blockIdx.z % HEADS;
    const int which = blockIdx.z / HEADS;
    float* buf = which ? k : q;
    const float* g = which ? (s < S_TXT ? gkc : gk) : (s < S_TXT ? gqc : gq);
    const float post = which ? 1.0f : SCALE;
    const int d = threadIdx.x;

    const size_t base = ((size_t)(b * SEQ + s)) * DIMN + h * HD;
    float v = buf[base + d];
    float ss = v * v;
    #pragma unroll
    for (int o = 16; o; o >>= 1) ss += __shfl_xor_sync(0xffffffffu, ss, o);
    __shared__ float wsum[4];
    __shared__ float nbuf[HD];
    if ((d & 31) == 0) wsum[d >> 5] = ss;
    __syncthreads();
    float tot = wsum[0] + wsum[1] + wsum[2] + wsum[3];
    float r = rsqrtf(tot * (1.0f / HD) + 1e-6f);
    nbuf[d] = v * r * g[d];
    __syncthreads();
    if (d < 64) {
        float x1 = nbuf[2 * d], x2 = nbuf[2 * d + 1];
        float c = cosb[s * 64 + d], sn = sinb[s * 64 + d];
        buf[base + 2 * d]     = __uint_as_float(f2tf((x1 * c - x2 * sn) * post));
        buf[base + 2 * d + 1] = __uint_as_float(f2tf((x1 * sn + x2 * c) * post));
    }
}

// ---------------- flash attention (tf32 mma via ldmatrix; V transposed) ----------------
#define QLD 132
#define KLD 132
#define VTLD 68
#define PLD 68

__global__ __launch_bounds__(256) void attn_mma(
    const float* __restrict__ Q, const float* __restrict__ K,
    const float* __restrict__ Vt, float* __restrict__ O)
{
    extern __shared__ float sm[];
    float* Qs = sm;                       // 128 x 132 (tf32, pre-scaled)
    float* Ks = Qs + 128 * QLD;           // 64 x 132  (tf32, rows = key)
    float* Vs = Ks + 64 * KLD;            // 128 x 68  (tf32, rows = d, cols = key)
    float* Ps = Vs + 128 * VTLD;          // 128 x 68

    const int t = threadIdx.x;
    const int lane = t & 31, w = t >> 5;
    const int g = lane >> 2, tig = lane & 3;
    const int mb = w * 16;
    const int m0 = blockIdx.x * 128;
    const int h = blockIdx.y;
    const int b = blockIdx.z;
    const size_t seqbase = (size_t)b * SEQ;

    const unsigned k_base = s2u(Ks);
    const unsigned v_base = s2u(Vs);
    // ldmatrix lane bases
    const unsigned q_lm = s2u(Qs) + (unsigned)((((mb + (lane & 15)) * QLD + ((lane >> 4) << 2))) * 4);
    const unsigned p_lm = s2u(Ps) + (unsigned)((((mb + (lane & 15)) * PLD + ((lane >> 4) << 2))) * 4);
    const unsigned k_lm = k_base + (unsigned)(((((lane & 7) + ((lane >> 4) << 3)) * KLD + (((lane >> 3) & 1) << 2))) * 4);
    const unsigned v_lm = v_base + (unsigned)(((((lane & 7) + ((lane >> 4) << 3)) * VTLD + (((lane >> 3) & 1) << 2))) * 4);

    const float* Qg = Q + (seqbase + m0) * DIMN + h * HD;
    for (int i = t; i < 128 * 32; i += 256) {
        int r = i >> 5, c4 = (i & 31) << 2;
        *(float4*)(Qs + r * QLD + c4) = *(const float4*)(Qg + (size_t)r * DIMN + c4);
    }

    const float* VgT = Vt + ((size_t)(b * HEADS + h) * HD) * SEQ;
    {
        const float* Kg = K + seqbase * DIMN + h * HD;
        #pragma unroll
        for (int j = 0; j < 8; j++) {
            int idx = j * 256 + t;
            int r = idx >> 5, c = (idx & 31) << 2;
            cpa16(k_base + (unsigned)((r * KLD + c) * 4), Kg + (size_t)r * DIMN + c);
        }
        cp_commit();
        #pragma unroll
        for (int j = 0; j < 8; j++) {
            int idx = j * 256 + t;
            int r = idx >> 4, c = (idx & 15) << 2;    // r = d (0..127), c = key (0..60)
            cpa16(v_base + (unsigned)((r * VTLD + c) * 4), VgT + (size_t)r * SEQ + c);
        }
        cp_commit();
    }

    float m0r = -1e30f, m1r = -1e30f, l0 = 0.f, l1 = 0.f;
    float o[16][4];
    #pragma unroll
    for (int nt = 0; nt < 16; nt++)
        #pragma unroll
        for (int i = 0; i < 4; i++) o[nt][i] = 0.f;

    for (int n0 = 0; n0 < SEQ; n0 += 64) {
        const bool has_next = (n0 + 64 < SEQ);
        cp_wait<1>();
        __syncthreads();

        // S = Q K^T (warp: 16x64) — ldmatrix fragments
        float s[8][4];
        #pragma unroll
        for (int nt = 0; nt < 8; nt++)
            #pragma unroll
            for (int i = 0; i < 4; i++) s[nt][i] = 0.f;
        #pragma unroll
        for (int kk = 0; kk < 16; kk++) {
            unsigned a0, a1, a2, a3;
            ldm_x4(a0, a1, a2, a3, q_lm + (unsigned)(kk * 32));
            #pragma unroll
            for (int ntp = 0; ntp < 4; ntp++) {
                unsigned b0, b1, b2, b3;
                ldm_x4(b0, b1, b2, b3, k_lm + (unsigned)(ntp * 16 * KLD * 4 + kk * 32));
                mma_tf32(s[2*ntp][0], s[2*ntp][1], s[2*ntp][2], s[2*ntp][3],
                         a0, a1, a2, a3, b0, b1);
                mma_tf32(s[2*ntp+1][0], s[2*ntp+1][1], s[2*ntp+1][2], s[2*ntp+1][3],
                         a0, a1, a2, a3, b2, b3);
            }
        }
        __syncthreads();

        if (has_next) {
            const float* Kg = K + (seqbase + n0 + 64) * DIMN + h * HD;
            #pragma unroll
            for (int j = 0; j < 8; j++) {
                int idx = j * 256 + t;
                int r = idx >> 5, c = (idx & 31) << 2;
                cpa16(k_base + (unsigned)((r * KLD + c) * 4), Kg + (size_t)r * DIMN + c);
            }
            cp_commit();
        }

        // online softmax (registers)
        float mx0 = -1e30f, mx1 = -1e30f;
        #pragma unroll
        for (int nt = 0; nt < 8; nt++) {
            mx0 = fmaxf(mx0, fmaxf(s[nt][0], s[nt][1]));
            mx1 = fmaxf(mx1, fmaxf(s[nt][2], s[nt][3]));
        }
        mx0 = fmaxf(mx0, __shfl_xor_sync(0xffffffffu, mx0, 1));
        mx0 = fmaxf(mx0, __shfl_xor_sync(0xffffffffu, mx0, 2));
        mx1 = fmaxf(mx1, __shfl_xor_sync(0xffffffffu, mx1, 1));
        mx1 = fmaxf(mx1, __shfl_xor_sync(0xffffffffu, mx1, 2));
        float mn0 = fmaxf(m0r, mx0), mn1 = fmaxf(m1r, mx1);
        float sc0 = __expf(m0r - mn0), sc1 = __expf(m1r - mn1);
        m0r = mn0; m1r = mn1;
        float sum0 = 0.f, sum1 = 0.f;
        #pragma unroll
        for (int nt = 0; nt < 8; nt++) {
            s[nt][0] = __expf(s[nt][0] - mn0); sum0 += s[nt][0];
            s[nt][1] = __expf(s[nt][1] - mn0); sum0 += s[nt][1];
            s[nt][2] = __expf(s[nt][2] - mn1); sum1 += s[nt][2];
            s[nt][3] = __expf(s[nt][3] - mn1); sum1 += s[nt][3];
        }
        sum0 += __shfl_xor_sync(0xffffffffu, sum0, 1);
        sum0 += __shfl_xor_sync(0xffffffffu, sum0, 2);
        sum1 += __shfl_xor_sync(0xffffffffu, sum1, 1);
        sum1 += __shfl_xor_sync(0xffffffffu, sum1, 2);
        l0 = l0 * sc0 + sum0;
        l1 = l1 * sc1 + sum1;

        #pragma unroll
        for (int nt = 0; nt < 8; nt++) {
            *(float2*)(Ps + (mb + g) * PLD + nt * 8 + 2 * tig) =
                make_float2(__uint_as_float(f2tf(s[nt][0])), __uint_as_float(f2tf(s[nt][1])));
            *(float2*)(Ps + (mb + g + 8) * PLD + nt * 8 + 2 * tig) =
                make_float2(__uint_as_float(f2tf(s[nt][2])), __uint_as_float(f2tf(s[nt][3])));
        }
        #pragma unroll
        for (int nt = 0; nt < 16; nt++) {
            o[nt][0] *= sc0; o[nt][1] *= sc0;
            o[nt][2] *= sc1; o[nt][3] *= sc1;
        }

        // tail: drain V(last) fully when no K-prefetch follows
        if (has_next) cp_wait<1>(); else cp_wait<0>();
        __syncthreads();

        // O += P @ V (warp: 16x128) — ldmatrix both operands
        #pragma unroll
        for (int kk = 0; kk < 8; kk++) {
            unsigned a0, a1, a2, a3;
            ldm_x4(a0, a1, a2, a3, p_lm + (unsigned)(kk * 32));
            #pragma unroll
            for (int ntp = 0; ntp < 8; ntp++) {
                unsigned b0, b1, b2, b3;
                ldm_x4(b0, b1, b2, b3, v_lm + (unsigned)(ntp * 16 * VTLD * 4 + kk * 32));
                mma_tf32(o[2*ntp][0], o[2*ntp][1], o[2*ntp][2], o[2*ntp][3],
                         a0, a1, a2, a3, b0, b1);
                mma_tf32(o[2*ntp+1][0], o[2*ntp+1][1], o[2*ntp+1][2], o[2*ntp+1][3],
                         a0, a1, a2, a3, b2, b3);
            }
        }
        __syncthreads();

        if (has_next) {
            #pragma unroll
            for (int j = 0; j < 8; j++) {
                int idx = j * 256 + t;
                int r = idx >> 4, c = (idx & 15) << 2;
                cpa16(v_base + (unsigned)((r * VTLD + c) * 4),
                      VgT + (size_t)r * SEQ + n0 + 64 + c);
            }
            cp_commit();
        }
    }

    // epilogue: write O as tf32 (consumed by out-projection GEMMs)
    float inv0 = 1.f / l0, inv1 = 1.f / l1;
    float* Og = O + (seqbase + m0 + mb) * DIMN + h * HD;
    #pragma unroll
    for (int nt = 0; nt < 16; nt++) {
        int col = nt * 8 + 2 * tig;
        *(float2*)(Og + (size_t)g * DIMN + col) =
            make_float2(__uint_as_float(f2tf(o[nt][0] * inv0)),
                        __uint_as_float(f2tf(o[nt][1] * inv0)));
        *(float2*)(Og + (size_t)(g + 8) * DIMN + col) =
            make_float2(__uint_as_float(f2tf(o[nt][2] * inv1)),
                        __uint_as_float(f2tf(o[nt][3] * inv1)));
    }
}

// ---------------- launch ----------------
extern "C" void kernel_launch(void* const* d_in, const int* in_sizes, int n_in,
                              void* d_out, int out_size)
{
    const float* x        = (const float*)d_in[0];
    const float* ctx      = (const float*)d_in[1];
    const float* rope_cos = (const float*)d_in[2];
    const float* rope_sin = (const float*)d_in[3];
    const float* wq   = (const float*)d_in[4];
    const float* bq   = (const float*)d_in[5];
    const float* wk   = (const float*)d_in[6];
    const float* bk   = (const float*)d_in[7];
    const float* wv   = (const float*)d_in[8];
    const float* bv   = (const float*)d_in[9];
    const float* wqc  = (const float*)d_in[10];
    const float* bqc  = (const float*)d_in[11];
    const float* wkc  = (const float*)d_in[12];
    const float* bkc  = (const float*)d_in[13];
    const float* wvc  = (const float*)d_in[14];
    const float* bvc  = (const float*)d_in[15];
    const float* w_out     = (const float*)d_in[16];
    const float* b_out     = (const float*)d_in[17];
    const float* w_add_out = (const float*)d_in[18];
    const float* b_add_out = (const float*)d_in[19];
    const float* g_q  = (const float*)d_in[20];
    const float* g_k  = (const float*)d_in[21];
    const float* g_qc = (const float*)d_in[22];
    const float* g_kc = (const float*)d_in[23];
    float* out = (float*)d_out;

    float *qb, *kb, *vtb, *ob, *wtf, *xtf, *ctxtf;
    cudaGetSymbolAddress((void**)&qb, g_qbuf);
    cudaGetSymbolAddress((void**)&kb, g_kbuf);
    cudaGetSymbolAddress((void**)&vtb, g_vtbuf);
    cudaGetSymbolAddress((void**)&ob, g_obuf);
    cudaGetSymbolAddress((void**)&wtf, g_wtf);
    cudaGetSymbolAddress((void**)&xtf, g_xtf);
    cudaGetSymbolAddress((void**)&ctxtf, g_ctxtf);

    const int smem_gemm = (NSTAGE * ASTAGE + NSTAGE * BSTAGE) * 4;
    const int smem_attn = (128 * QLD + 64 * KLD + 128 * VTLD + 128 * PLD) * 4;
    cudaFuncSetAttribute(gemm_tf32, cudaFuncAttributeMaxDynamicSharedMemorySize, smem_gemm);
    cudaFuncSetAttribute(attn_mma, cudaFuncAttributeMaxDynamicSharedMemorySize, smem_attn);

    // ---- tf32 pre-conversion (weights + activations) ----
    const int CVB = 592;  // 148 SMs * 4
    cvt_tf32<<<CVB, 256>>>(wq,        wtf + 0 * (size_t)M2, M2 / 4);
    cvt_tf32<<<CVB, 256>>>(wk,        wtf + 1 * (size_t)M2, M2 / 4);
    cvt_tf32<<<CVB, 256>>>(wv,        wtf + 2 * (size_t)M2, M2 / 4);
    cvt_tf32<<<CVB, 256>>>(wqc,       wtf + 3 * (size_t)M2, M2 / 4);
    cvt_tf32<<<CVB, 256>>>(wkc,       wtf + 4 * (size_t)M2, M2 / 4);
    cvt_tf32<<<CVB, 256>>>(wvc,       wtf + 5 * (size_t)M2, M2 / 4);
    cvt_tf32<<<CVB, 256>>>(w_out,     wtf + 6 * (size_t)M2, M2 / 4);
    cvt_tf32<<<CVB, 256>>>(w_add_out, wtf + 7 * (size_t)M2, M2 / 4);
    cvt_tf32<<<CVB, 256>>>(x,   xtf,   BATCH * S_IMG * DIMN / 4);
    cvt_tf32<<<CVB, 256>>>(ctx, ctxtf, BATCH * S_TXT * DIMN / 4);

    dim3 blk(256);
    // fused QKV projections; z=2 (V) writes transposed tf32 into vtb
    dim3 grid_ctx3(DIMN / 128, (BATCH * S_TXT) / 128, 3);
    dim3 grid_img3(DIMN / 128, (BATCH * S_IMG) / 128, 3);
    gemm_tf32<<<grid_ctx3, blk, smem_gemm>>>(ctxtf,
        wtf + 3 * (size_t)M2, wtf + 4 * (size_t)M2, wtf + 5 * (size_t)M2,
        bqc, bkc, bvc, qb, kb, vtb, S_TXT, S_TXT, 0, SEQ, 0, 4, 4);
    gemm_tf32<<<grid_img3, blk, smem_gemm>>>(xtf,
        wtf + 0 * (size_t)M2, wtf + 1 * (size_t)M2, wtf + 2 * (size_t)M2,
        bq, bk, bv, qb, kb, vtb, S_IMG, S_IMG, 0, SEQ, S_TXT, 4, 4);

    dim3 grid_rr(SEQ, BATCH, 2 * HEADS);
    rmsrope_kernel<<<grid_rr, 128>>>(qb, kb, rope_cos, rope_sin, g_q, g_qc, g_k, g_kc);

    dim3 grid_at(SEQ / 128, HEADS, BATCH);
    attn_mma<<<grid_at, blk, smem_attn>>>(qb, kb, vtb, ob);

    dim3 grid_txt(DIMN / 128, (BATCH * S_TXT) / 128, 1);
    dim3 grid_img(DIMN / 128, (BATCH * S_IMG) / 128, 1);
    gemm_tf32<<<grid_txt, blk, smem_gemm>>>(ob,
        wtf + 7 * (size_t)M2, wtf + 7 * (size_t)M2, wtf + 7 * (size_t)M2,
        b_add_out, b_add_out, b_add_out,
        out, out, out, S_TXT, SEQ, 0, S_TXT, 0, 0, 0);
    gemm_tf32<<<grid_img, blk, smem_gemm>>>(ob,
        wtf + 6 * (size_t)M2, wtf + 6 * (size_t)M2, wtf + 6 * (size_t)M2,
        b_out, b_out, b_out,
        out + (size_t)BATCH * S_TXT * DIMN,
        out + (size_t)BATCH * S_TXT * DIMN,
        out + (size_t)BATCH * S_TXT * DIMN,
        S_IMG, SEQ, S_TXT, S_IMG, 0, 0, 0);
}